// round 11
// baseline (speedup 1.0000x reference)
#include <cuda_runtime.h>

// Ragged segment mean — even-split NSPLIT=8, unroll x8, NC loads with
// L2::256B prefetch hint, REDG.v4 merge into memset-zeroed out.
//   seq:   [B=2048, L=512, D=512] fp32   (d_in[0])
//   begin: [B] int32                      (d_in[1])
//   end:   [B] int32                      (d_in[2])
//   out:   [B, D] fp32 = mean(seq[b, begin[b]:end[b], :], axis=0)
//
// Grid = B*8 linear CTAs; CTA id -> (b = id>>3, c = id&7); chunk c covers
// [begin + len*c/8, begin + len*(c+1)/8)  (<=32 rows, no empties).
// Loads use ld.global.nc.L2::256B.v4.f32 (read-only path + 256B sector
// prefetch) to raise DRAM burst efficiency on the streaming read.

#define B_DIM   2048
#define L_DIM   512
#define D_DIM   512
#define THREADS 128          // D_DIM / 4 lanes of float4
#define NSPLIT  8
#define ROWS4   (D_DIM / 4)  // row stride in float4 units = 128

__device__ __forceinline__ float4 ldg_nc_256(const float4* p) {
    float4 v;
    asm volatile("ld.global.nc.L2::256B.v4.f32 {%0, %1, %2, %3}, [%4];"
                 : "=f"(v.x), "=f"(v.y), "=f"(v.z), "=f"(v.w)
                 : "l"(p));
    return v;
}

__global__ __launch_bounds__(THREADS)
void ragged_mean_chunk_kernel(const float* __restrict__ seq,
                              const int* __restrict__ begin,
                              const int* __restrict__ end,
                              float* __restrict__ out) {
    const int id = blockIdx.x;
    const int b  = id >> 3;            // id / NSPLIT
    const int c  = id & (NSPLIT - 1);  // id % NSPLIT
    const int t  = threadIdx.x;        // owns columns [4t, 4t+4)

    const int sb  = begin[b];
    const int eb  = end[b];
    const int len = eb - sb;           // in [1, 256]

    const int s = sb + (len * c) / NSPLIT;
    const int e = sb + (len * (c + 1)) / NSPLIT;
    if (s >= e) return;                // only when len < NSPLIT

    const float4* base =
        reinterpret_cast<const float4*>(seq + (size_t)b * L_DIM * D_DIM) + t;

    // Two accumulator trees to keep FADD chains short.
    float ax0 = 0.f, ay0 = 0.f, az0 = 0.f, aw0 = 0.f;
    float ax1 = 0.f, ay1 = 0.f, az1 = 0.f, aw1 = 0.f;

    int l = s;
    // Main loop: 8 independent LDG.128 per thread per iteration.
    for (; l + 8 <= e; l += 8) {
        float4 v0 = ldg_nc_256(&base[(size_t)(l + 0) * ROWS4]);
        float4 v1 = ldg_nc_256(&base[(size_t)(l + 1) * ROWS4]);
        float4 v2 = ldg_nc_256(&base[(size_t)(l + 2) * ROWS4]);
        float4 v3 = ldg_nc_256(&base[(size_t)(l + 3) * ROWS4]);
        float4 v4 = ldg_nc_256(&base[(size_t)(l + 4) * ROWS4]);
        float4 v5 = ldg_nc_256(&base[(size_t)(l + 5) * ROWS4]);
        float4 v6 = ldg_nc_256(&base[(size_t)(l + 6) * ROWS4]);
        float4 v7 = ldg_nc_256(&base[(size_t)(l + 7) * ROWS4]);
        ax0 += v0.x + v1.x + v2.x + v3.x;
        ay0 += v0.y + v1.y + v2.y + v3.y;
        az0 += v0.z + v1.z + v2.z + v3.z;
        aw0 += v0.w + v1.w + v2.w + v3.w;
        ax1 += v4.x + v5.x + v6.x + v7.x;
        ay1 += v4.y + v5.y + v6.y + v7.y;
        az1 += v4.z + v5.z + v6.z + v7.z;
        aw1 += v4.w + v5.w + v6.w + v7.w;
    }
    if (l + 4 <= e) {
        float4 v0 = ldg_nc_256(&base[(size_t)(l + 0) * ROWS4]);
        float4 v1 = ldg_nc_256(&base[(size_t)(l + 1) * ROWS4]);
        float4 v2 = ldg_nc_256(&base[(size_t)(l + 2) * ROWS4]);
        float4 v3 = ldg_nc_256(&base[(size_t)(l + 3) * ROWS4]);
        ax0 += v0.x + v1.x + v2.x + v3.x;
        ay0 += v0.y + v1.y + v2.y + v3.y;
        az0 += v0.z + v1.z + v2.z + v3.z;
        aw0 += v0.w + v1.w + v2.w + v3.w;
        l += 4;
    }
    for (; l < e; ++l) {
        float4 v = ldg_nc_256(&base[(size_t)l * ROWS4]);
        ax1 += v.x; ay1 += v.y; az1 += v.z; aw1 += v.w;
    }

    const float inv = 1.0f / (float)len;
    const float ax = (ax0 + ax1) * inv;
    const float ay = (ay0 + ay1) * inv;
    const float az = (az0 + az1) * inv;
    const float aw = (aw0 + aw1) * inv;

    float* dst = out + (size_t)b * D_DIM + 4 * t;  // 16B aligned
    asm volatile("red.global.add.v4.f32 [%0], {%1, %2, %3, %4};"
                 :: "l"(dst), "f"(ax), "f"(ay), "f"(az), "f"(aw)
                 : "memory");
}

extern "C" void kernel_launch(void* const* d_in, const int* in_sizes, int n_in,
                              void* d_out, int out_size) {
    const float* seq   = (const float*)d_in[0];
    const int*   begin = (const int*)d_in[1];
    const int*   end   = (const int*)d_in[2];
    float*       out   = (float*)d_out;

    // Zero the accumulation target (async, graph-capturable)
    cudaMemsetAsync(d_out, 0, (size_t)B_DIM * D_DIM * sizeof(float));

    ragged_mean_chunk_kernel<<<B_DIM * NSPLIT, THREADS>>>(seq, begin, end, out);
}

// round 12
// speedup vs baseline: 1.0104x; 1.0104x over previous
#include <cuda_runtime.h>

// Ragged segment mean — even-split NSPLIT=8 with 8-row-ALIGNED boundaries,
// unroll x8 NC loads, REDG.v4 merge into memset-zeroed out.
//   seq:   [B=2048, L=512, D=512] fp32   (d_in[0])
//   begin: [B] int32                      (d_in[1])
//   end:   [B] int32                      (d_in[2])
//   out:   [B, D] fp32 = mean(seq[b, begin[b]:end[b], :], axis=0)
//
// Grid = B*8 linear CTAs; CTA id -> (b = id>>3, c = id&7). Split points
// r(c) = floor(len*c/8) & ~7 (r0=0, r8=len): every interior chunk is an
// exact multiple of 8 rows, so 7 of 8 chunks run the pure unroll-8 path
// with no MLP=1 tail drain; only the last chunk handles a <8-row tail.

#define B_DIM   2048
#define L_DIM   512
#define D_DIM   512
#define THREADS 128          // D_DIM / 4 lanes of float4
#define NSPLIT  8
#define ROWS4   (D_DIM / 4)  // row stride in float4 units = 128

__device__ __forceinline__ float4 ldg_nc_256(const float4* p) {
    float4 v;
    asm volatile("ld.global.nc.L2::256B.v4.f32 {%0, %1, %2, %3}, [%4];"
                 : "=f"(v.x), "=f"(v.y), "=f"(v.z), "=f"(v.w)
                 : "l"(p));
    return v;
}

__global__ __launch_bounds__(THREADS)
void ragged_mean_chunk_kernel(const float* __restrict__ seq,
                              const int* __restrict__ begin,
                              const int* __restrict__ end,
                              float* __restrict__ out) {
    const int id = blockIdx.x;
    const int b  = id >> 3;            // id / NSPLIT
    const int c  = id & (NSPLIT - 1);  // id % NSPLIT
    const int t  = threadIdx.x;        // owns columns [4t, 4t+4)

    const int sb  = begin[b];
    const int eb  = end[b];
    const int len = eb - sb;           // in [1, 256]

    // 8-row-aligned interior split points; exact coverage of [0, len).
    const int r0 = (c == 0)          ? 0   : (((len * c) >> 3) & ~7);
    const int r1 = (c == NSPLIT - 1) ? len : (((len * (c + 1)) >> 3) & ~7);
    if (r0 >= r1) return;              // empty chunk (short segments)

    const int s = sb + r0;
    const int e = sb + r1;

    const float4* base =
        reinterpret_cast<const float4*>(seq + (size_t)b * L_DIM * D_DIM) + t;

    // Two accumulator trees to keep FADD chains short.
    float ax0 = 0.f, ay0 = 0.f, az0 = 0.f, aw0 = 0.f;
    float ax1 = 0.f, ay1 = 0.f, az1 = 0.f, aw1 = 0.f;

    int l = s;
    // Main loop: 8 independent LDG.128 per thread per iteration.
    for (; l + 8 <= e; l += 8) {
        float4 v0 = ldg_nc_256(&base[(size_t)(l + 0) * ROWS4]);
        float4 v1 = ldg_nc_256(&base[(size_t)(l + 1) * ROWS4]);
        float4 v2 = ldg_nc_256(&base[(size_t)(l + 2) * ROWS4]);
        float4 v3 = ldg_nc_256(&base[(size_t)(l + 3) * ROWS4]);
        float4 v4 = ldg_nc_256(&base[(size_t)(l + 4) * ROWS4]);
        float4 v5 = ldg_nc_256(&base[(size_t)(l + 5) * ROWS4]);
        float4 v6 = ldg_nc_256(&base[(size_t)(l + 6) * ROWS4]);
        float4 v7 = ldg_nc_256(&base[(size_t)(l + 7) * ROWS4]);
        ax0 += v0.x + v1.x + v2.x + v3.x;
        ay0 += v0.y + v1.y + v2.y + v3.y;
        az0 += v0.z + v1.z + v2.z + v3.z;
        aw0 += v0.w + v1.w + v2.w + v3.w;
        ax1 += v4.x + v5.x + v6.x + v7.x;
        ay1 += v4.y + v5.y + v6.y + v7.y;
        az1 += v4.z + v5.z + v6.z + v7.z;
        aw1 += v4.w + v5.w + v6.w + v7.w;
    }
    // Tail: only the last chunk of a segment can reach here (<8 rows).
    if (l + 4 <= e) {
        float4 v0 = ldg_nc_256(&base[(size_t)(l + 0) * ROWS4]);
        float4 v1 = ldg_nc_256(&base[(size_t)(l + 1) * ROWS4]);
        float4 v2 = ldg_nc_256(&base[(size_t)(l + 2) * ROWS4]);
        float4 v3 = ldg_nc_256(&base[(size_t)(l + 3) * ROWS4]);
        ax0 += v0.x + v1.x + v2.x + v3.x;
        ay0 += v0.y + v1.y + v2.y + v3.y;
        az0 += v0.z + v1.z + v2.z + v3.z;
        aw0 += v0.w + v1.w + v2.w + v3.w;
        l += 4;
    }
    for (; l < e; ++l) {
        float4 v = ldg_nc_256(&base[(size_t)l * ROWS4]);
        ax1 += v.x; ay1 += v.y; az1 += v.z; aw1 += v.w;
    }

    const float inv = 1.0f / (float)len;
    const float ax = (ax0 + ax1) * inv;
    const float ay = (ay0 + ay1) * inv;
    const float az = (az0 + az1) * inv;
    const float aw = (aw0 + aw1) * inv;

    float* dst = out + (size_t)b * D_DIM + 4 * t;  // 16B aligned
    asm volatile("red.global.add.v4.f32 [%0], {%1, %2, %3, %4};"
                 :: "l"(dst), "f"(ax), "f"(ay), "f"(az), "f"(aw)
                 : "memory");
}

extern "C" void kernel_launch(void* const* d_in, const int* in_sizes, int n_in,
                              void* d_out, int out_size) {
    const float* seq   = (const float*)d_in[0];
    const int*   begin = (const int*)d_in[1];
    const int*   end   = (const int*)d_in[2];
    float*       out   = (float*)d_out;

    // Zero the accumulation target (async, graph-capturable)
    cudaMemsetAsync(d_out, 0, (size_t)B_DIM * D_DIM * sizeof(float));

    ragged_mean_chunk_kernel<<<B_DIM * NSPLIT, THREADS>>>(seq, begin, end, out);
}

// round 13
// speedup vs baseline: 1.0563x; 1.0454x over previous
#include <cuda_runtime.h>

// Ragged segment mean — consolidated best config:
//   __ldcs loads (NC path consistently lost ~4us e2e at natural clocks),
//   unroll x8 dual accumulator trees, 8-row-aligned even-split (NSPLIT=8),
//   dim3(B,8) grid, memset zero-init, red.global.add.v4.f32 merge.
//   seq:   [B=2048, L=512, D=512] fp32   (d_in[0])
//   begin: [B] int32                      (d_in[1])
//   end:   [B] int32                      (d_in[2])
//   out:   [B, D] fp32 = mean(seq[b, begin[b]:end[b], :], axis=0)
//
// Split points r(c) = floor(len*c/8) & ~7 (r0=0, r8=len): interior chunks
// are exact multiples of 8 rows -> pure unroll-8 path, no MLP=1 tail;
// only the last chunk of each segment handles a <8-row remainder.

#define B_DIM   2048
#define L_DIM   512
#define D_DIM   512
#define THREADS 128          // D_DIM / 4 lanes of float4
#define NSPLIT  8
#define ROWS4   (D_DIM / 4)  // row stride in float4 units = 128

__global__ __launch_bounds__(THREADS)
void ragged_mean_chunk_kernel(const float* __restrict__ seq,
                              const int* __restrict__ begin,
                              const int* __restrict__ end,
                              float* __restrict__ out) {
    const int b = blockIdx.x;
    const int c = blockIdx.y;
    const int t = threadIdx.x;         // owns columns [4t, 4t+4)

    const int sb  = begin[b];
    const int eb  = end[b];
    const int len = eb - sb;           // in [1, 256]

    // 8-row-aligned interior split points; exact coverage of [0, len).
    const int r0 = (c == 0)          ? 0   : (((len * c) >> 3) & ~7);
    const int r1 = (c == NSPLIT - 1) ? len : (((len * (c + 1)) >> 3) & ~7);
    if (r0 >= r1) return;              // empty chunk (short segments)

    const int s = sb + r0;
    const int e = sb + r1;

    const float4* base =
        reinterpret_cast<const float4*>(seq + (size_t)b * L_DIM * D_DIM) + t;

    // Two accumulator trees to keep FADD chains short.
    float ax0 = 0.f, ay0 = 0.f, az0 = 0.f, aw0 = 0.f;
    float ax1 = 0.f, ay1 = 0.f, az1 = 0.f, aw1 = 0.f;

    int l = s;
    // Main loop: 8 independent LDG.128 per thread per iteration.
    for (; l + 8 <= e; l += 8) {
        float4 v0 = __ldcs(&base[(size_t)(l + 0) * ROWS4]);
        float4 v1 = __ldcs(&base[(size_t)(l + 1) * ROWS4]);
        float4 v2 = __ldcs(&base[(size_t)(l + 2) * ROWS4]);
        float4 v3 = __ldcs(&base[(size_t)(l + 3) * ROWS4]);
        float4 v4 = __ldcs(&base[(size_t)(l + 4) * ROWS4]);
        float4 v5 = __ldcs(&base[(size_t)(l + 5) * ROWS4]);
        float4 v6 = __ldcs(&base[(size_t)(l + 6) * ROWS4]);
        float4 v7 = __ldcs(&base[(size_t)(l + 7) * ROWS4]);
        ax0 += v0.x + v1.x + v2.x + v3.x;
        ay0 += v0.y + v1.y + v2.y + v3.y;
        az0 += v0.z + v1.z + v2.z + v3.z;
        aw0 += v0.w + v1.w + v2.w + v3.w;
        ax1 += v4.x + v5.x + v6.x + v7.x;
        ay1 += v4.y + v5.y + v6.y + v7.y;
        az1 += v4.z + v5.z + v6.z + v7.z;
        aw1 += v4.w + v5.w + v6.w + v7.w;
    }
    // Tail: only the last chunk of a segment can reach here (<8 rows).
    if (l + 4 <= e) {
        float4 v0 = __ldcs(&base[(size_t)(l + 0) * ROWS4]);
        float4 v1 = __ldcs(&base[(size_t)(l + 1) * ROWS4]);
        float4 v2 = __ldcs(&base[(size_t)(l + 2) * ROWS4]);
        float4 v3 = __ldcs(&base[(size_t)(l + 3) * ROWS4]);
        ax0 += v0.x + v1.x + v2.x + v3.x;
        ay0 += v0.y + v1.y + v2.y + v3.y;
        az0 += v0.z + v1.z + v2.z + v3.z;
        aw0 += v0.w + v1.w + v2.w + v3.w;
        l += 4;
    }
    for (; l < e; ++l) {
        float4 v = __ldcs(&base[(size_t)l * ROWS4]);
        ax1 += v.x; ay1 += v.y; az1 += v.z; aw1 += v.w;
    }

    const float inv = 1.0f / (float)len;
    const float ax = (ax0 + ax1) * inv;
    const float ay = (ay0 + ay1) * inv;
    const float az = (az0 + az1) * inv;
    const float aw = (aw0 + aw1) * inv;

    float* dst = out + (size_t)b * D_DIM + 4 * t;  // 16B aligned
    asm volatile("red.global.add.v4.f32 [%0], {%1, %2, %3, %4};"
                 :: "l"(dst), "f"(ax), "f"(ay), "f"(az), "f"(aw)
                 : "memory");
}

extern "C" void kernel_launch(void* const* d_in, const int* in_sizes, int n_in,
                              void* d_out, int out_size) {
    const float* seq   = (const float*)d_in[0];
    const int*   begin = (const int*)d_in[1];
    const int*   end   = (const int*)d_in[2];
    float*       out   = (float*)d_out;

    // Zero the accumulation target (async, graph-capturable)
    cudaMemsetAsync(d_out, 0, (size_t)B_DIM * D_DIM * sizeof(float));

    dim3 grid(B_DIM, NSPLIT);
    ragged_mean_chunk_kernel<<<grid, THREADS>>>(seq, begin, end, out);
}